// round 12
// baseline (speedup 1.0000x reference)
#include <cuda_runtime.h>
#include <cstddef>
#include <cstdint>

// Problem constants
#define Bn 8
#define Tn 512
#define Nn 64
#define Hn 256   // I == H == 256

typedef unsigned long long ull;

// ---------------------------------------------------------------------------
// Scratch (device globals: allocation-free rule)
// ---------------------------------------------------------------------------
__device__ float g_xin[(size_t)Bn * Tn * Nn * Hn];   // per-layer input projections
__device__ float g_y0 [(size_t)Bn * Tn * Nn * Hn];   // layer-0 outputs

// f32x2 packed helpers -------------------------------------------------------
__device__ __forceinline__ ull dup_f32(float x) {
    ull r;
    asm("mov.b64 %0, {%1, %1};" : "=l"(r) : "f"(x));
    return r;
}
__device__ __forceinline__ void fma2(ull& acc, ull a, ull b) {
    asm("fma.rn.f32x2 %0, %1, %2, %0;" : "+l"(acc) : "l"(a), "l"(b));
}
__device__ __forceinline__ void add2(ull& acc, ull v) {
    asm("add.rn.f32x2 %0, %0, %1;" : "+l"(acc) : "l"(v));
}
__device__ __forceinline__ void unpack2(ull v, float& lo, float& hi) {
    asm("mov.b64 {%0, %1}, %2;" : "=f"(lo), "=f"(hi) : "l"(v));
}
__device__ __forceinline__ ull pack2(float lo, float hi) {
    ull r;
    asm("mov.b64 %0, {%1, %2};" : "=l"(r) : "f"(lo), "f"(hi));
    return r;
}
__device__ __forceinline__ uint32_t smem_u32(const void* p) {
    uint32_t a;
    asm("{ .reg .u64 t; cvta.to.shared.u64 t, %1; cvt.u32.u64 %0, t; }"
        : "=r"(a) : "l"(p));
    return a;
}

// ---------------------------------------------------------------------------
// Projection (f32x2): g_xin[b,m,j] = sum_i X[b,m,i]*W[b,j,i] + b_ih[b,j] + b_hh[b,j]
//   M = T*N = 32768, K = 256, J = 256; 64m x 64j tile, 256 threads.
//   SMEM k-major: Xs[32][64], Ws[32][64].
//   Per thread: 4m x 4j (j as pairs at tx2 and tx2+32).
//   Per k: LDS.128 x (broadcast) + 2x LDS.64 w (conflict-free) + 4 dup + 8 FFMA2.
// ---------------------------------------------------------------------------
__global__ __launch_bounds__(256) void proj_kernel(
    const float* __restrict__ Xext,
    const float* __restrict__ W,
    const float* __restrict__ bih,
    const float* __restrict__ bhh)
{
    __shared__ float Xs[32 * 64];
    __shared__ float Ws[32 * 64];

    const float* X = Xext ? Xext : g_y0;
    const int mt = blockIdx.x, jt = blockIdx.y, b = blockIdx.z;
    const int lin = threadIdx.x;
    const int tx = lin & 15, ty = lin >> 4;
    const int tx2 = tx * 2, ty4 = ty * 4;

    const float* Xb = X + ((size_t)b * (Tn * Nn) + mt * 64) * 256;
    const float* Wb = W + ((size_t)b * 256 + jt * 64) * 256;

    ull a00 = 0, a01 = 0, a10 = 0, a11 = 0, a20 = 0, a21 = 0, a30 = 0, a31 = 0;

    for (int kk = 0; kk < 256; kk += 32) {
        // Stage (transpose to k-major). Mapping: lanes vary m for fixed k
        // -> STS conflict-free (m stride 1 across banks).
#pragma unroll
        for (int r = 0; r < 2; ++r) {
            int f  = lin + r * 256;          // 0..511 = 64 rows x 8 k-quads
            int m  = f & 63;
            int kc = (f >> 6) << 2;
            float4 xv = *(const float4*)(Xb + (size_t)m * 256 + kk + kc);
            Xs[(kc + 0) * 64 + m] = xv.x;
            Xs[(kc + 1) * 64 + m] = xv.y;
            Xs[(kc + 2) * 64 + m] = xv.z;
            Xs[(kc + 3) * 64 + m] = xv.w;
            float4 wv = *(const float4*)(Wb + (size_t)m * 256 + kk + kc);
            Ws[(kc + 0) * 64 + m] = wv.x;
            Ws[(kc + 1) * 64 + m] = wv.y;
            Ws[(kc + 2) * 64 + m] = wv.z;
            Ws[(kc + 3) * 64 + m] = wv.w;
        }
        __syncthreads();

#pragma unroll
        for (int k = 0; k < 32; ++k) {
            float4 xv = *(const float4*)(Xs + k * 64 + ty4);
            ull w0 = *(const ull*)(Ws + k * 64 + tx2);
            ull w1 = *(const ull*)(Ws + k * 64 + tx2 + 32);
            ull d0 = dup_f32(xv.x), d1 = dup_f32(xv.y);
            ull d2 = dup_f32(xv.z), d3 = dup_f32(xv.w);
            fma2(a00, d0, w0); fma2(a01, d0, w1);
            fma2(a10, d1, w0); fma2(a11, d1, w1);
            fma2(a20, d2, w0); fma2(a21, d2, w1);
            fma2(a30, d3, w0); fma2(a31, d3, w1);
        }
        __syncthreads();
    }

    // Epilogue: add bias, store float2 pairs (coalesced per warp)
    const int j0 = jt * 64 + tx2, j1 = j0 + 32;
    float2 bi0 = *(const float2*)(bih + b * 256 + j0);
    float2 bh0 = *(const float2*)(bhh + b * 256 + j0);
    float2 bi1 = *(const float2*)(bih + b * 256 + j1);
    float2 bh1 = *(const float2*)(bhh + b * 256 + j1);
    const float b00 = bi0.x + bh0.x, b01 = bi0.y + bh0.y;
    const float b10 = bi1.x + bh1.x, b11 = bi1.y + bh1.y;

    const size_t mbase = (size_t)b * (Tn * Nn) + mt * 64 + ty4;
    ull accs[4][2] = {{a00, a01}, {a10, a11}, {a20, a21}, {a30, a31}};
#pragma unroll
    for (int i = 0; i < 4; ++i) {
        float lo, hi;
        unpack2(accs[i][0], lo, hi);
        *(float2*)(g_xin + (mbase + i) * 256 + j0) = make_float2(lo + b00, hi + b01);
        unpack2(accs[i][1], lo, hi);
        *(float2*)(g_xin + (mbase + i) * 256 + j1) = make_float2(lo + b10, hi + b11);
    }
}

// ---------------------------------------------------------------------------
// Recurrence: 512 sequential steps. (UNCHANGED from R10 — best known)
//   64 clusters of 2 CTAs. Cluster = (instance b, n-octet). CTA = j-half (128 j).
//   Per-CTA: 8n x 128j x 256k per step; W half (128x256 f32) resident in SMEM.
//   h lives in SMEM (double-buffered [2][256][10]); per step each CTA writes its
//   8n x 128j half locally AND into the peer via DSMEM (st.shared::cluster).
//   256 threads, k-split: kh=lin>>7 does k in [kh*128, kh*128+128).
//   Thread micro: 2n x 4j. Per k: LDS.64 h + LDS.128 w + 2 dup + 4 FFMA2.
// ---------------------------------------------------------------------------
#define WP 132   // w_s row stride (floats)
#define HP 10    // h_buf row stride (floats)

__global__ __launch_bounds__(256) __cluster_dims__(2, 1, 1)
void rec_kernel(
    const float* __restrict__ hx,     // [B, L, N, H]
    const float* __restrict__ whh,    // [B, H, H]
    float* __restrict__ yext,         // layer outputs (nullptr -> g_y0)
    float* __restrict__ hn,           // [B, L, N, H] final hidden
    int layer)
{
    extern __shared__ float sm[];
    float* w_s  = sm;                       // [256][WP]  k-major, j-half fast
    float* hbuf = sm + 256 * WP;            // [2][256][HP] k = GLOBAL j index
    ull* red = (ull*)(sm + 256 * WP + 2 * 256 * HP);  // [128][4]

    const int jh  = blockIdx.x;             // j-half = cluster rank (0/1)
    const int bn  = blockIdx.y;             // b*8 + n-octet
    const int b   = bn >> 3, nch = bn & 7;
    const int lin = threadIdx.x;
    const int kh  = lin >> 7;               // k-half (warp-uniform)
    const int wl  = lin & 127;
    const int jc  = wl >> 5;                // j-chunk of 32 within half (0..3)
    const int lane = wl & 31;
    const int q   = lane & 7;               // j-quad (0..7)
    const int p   = lane >> 3;              // n-pair (0..3)
    const int jl  = jc * 32 + q * 4;        // j within half (0..124)
    const int p2  = p * 2;
    const int kbeg = kh << 7;

    float* y = yext ? yext : g_y0;

    // Resident W half, transposed k-major: w_s[k][j] = whh[b][jh*128+j][k]
    const float* wb = whh + ((size_t)b * 256 + jh * 128) * 256;
    for (int f = lin; f < 8192; f += 256) {       // 128 j x 64 float4
        int j = f >> 6, kc = (f & 63) << 2;
        float4 v = *(const float4*)(wb + (size_t)j * 256 + kc);
        w_s[(kc + 0) * WP + j] = v.x;
        w_s[(kc + 1) * WP + j] = v.y;
        w_s[(kc + 2) * WP + j] = v.z;
        w_s[(kc + 3) * WP + j] = v.w;
    }

    // t=0 h staging: full 256-k rows for our 8 n, transposed into hbuf[1]
    const float* h0 = hx + (size_t)(b * 2 + layer) * Nn * Hn + (size_t)nch * 8 * Hn;
    for (int f = lin; f < 2048; f += 256) {       // 8 n x 256 k scalars
        int n = f >> 8, k = f & 255;
        hbuf[(size_t)(256 + k) * HP + n] = h0[n * 256 + k];   // buffer 1
    }
    __syncthreads();

    // Peer DSMEM base for hbuf
    const uint32_t hbuf_local = smem_u32(hbuf);
    uint32_t hbuf_peer;
    asm("mapa.shared::cluster.u32 %0, %1, %2;"
        : "=r"(hbuf_peer) : "r"(hbuf_local), "r"(jh ^ 1));

    const int jrow0 = jh * 128 + jl;        // global j row base for our outputs
    const size_t xybase0 = (size_t)nch * 8 * Hn + jh * 128 + jl;

    for (int t = 0; t < Tn; ++t) {
        const float* hcur = hbuf + (size_t)(((t + 1) & 1) * 256) * HP;

        // Prefetch xin[t] fragment (lower half owns the epilogue)
        const size_t tb = ((size_t)b * Tn + t) * (Nn * Hn) + xybase0;
        float4 x0, x1;
        if (!kh) {
            x0 = __ldg((const float4*)(g_xin + tb + (size_t)(p2 + 0) * Hn));
            x1 = __ldg((const float4*)(g_xin + tb + (size_t)(p2 + 1) * Hn));
        }

        // Packed-f32x2 mainloop over this thread's k-half
        ull a00 = 0ull, a01 = 0ull, a10 = 0ull, a11 = 0ull;
#pragma unroll 8
        for (int k = kbeg; k < kbeg + 128; ++k) {
            float2 hv = *(const float2*)(hcur + (size_t)k * HP + p2);
            ulonglong2 wv = *(const ulonglong2*)(w_s + (size_t)k * WP + jl);
            ull h0d = dup_f32(hv.x);
            ull h1d = dup_f32(hv.y);
            fma2(a00, h0d, wv.x);
            fma2(a01, h0d, wv.y);
            fma2(a10, h1d, wv.x);
            fma2(a11, h1d, wv.y);
        }

        // Cross-half reduction through SMEM scratch
        if (kh) {
            ulonglong2* r = (ulonglong2*)(red + (size_t)wl * 4);
            r[0] = make_ulonglong2(a00, a01);
            r[1] = make_ulonglong2(a10, a11);
        }
        __syncthreads();

        if (!kh) {
            const ulonglong2* r = (const ulonglong2*)(red + (size_t)wl * 4);
            ulonglong2 q0 = r[0], q1 = r[1];
            add2(a00, q0.x); add2(a01, q0.y);
            add2(a10, q1.x); add2(a11, q1.y);

            float f00, f01, f02, f03, f10, f11, f12, f13;
            unpack2(a00, f00, f01); unpack2(a01, f02, f03);
            unpack2(a10, f10, f11); unpack2(a11, f12, f13);

            float4 v0, v1;
            v0.x = tanhf(f00 + x0.x); v0.y = tanhf(f01 + x0.y);
            v0.z = tanhf(f02 + x0.z); v0.w = tanhf(f03 + x0.w);
            v1.x = tanhf(f10 + x1.x); v1.y = tanhf(f11 + x1.y);
            v1.z = tanhf(f12 + x1.z); v1.w = tanhf(f13 + x1.w);

            // y (and hn) global stores
            float* yt = y + ((size_t)b * Tn + t) * (Nn * Hn) + xybase0;
            *(float4*)(yt + (size_t)(p2 + 0) * Hn) = v0;
            *(float4*)(yt + (size_t)(p2 + 1) * Hn) = v1;
            if (t == Tn - 1) {
                float* hnp = hn + (size_t)(b * 2 + layer) * Nn * Hn + xybase0;
                *(float4*)(hnp + (size_t)(p2 + 0) * Hn) = v0;
                *(float4*)(hnp + (size_t)(p2 + 1) * Hn) = v1;
            }

            // h stores: local + peer DSMEM, rows = global j, cols = local n-pair
            const int boff = (t & 1) * 256;
            float* hl = hbuf + (size_t)(boff + jrow0) * HP + p2;
            const uint32_t rbase = hbuf_peer
                + (uint32_t)(((boff + jrow0) * HP + p2) * sizeof(float));
            ull pk;

            *(float2*)(hl + 0 * HP) = make_float2(v0.x, v1.x);
            pk = pack2(v0.x, v1.x);
            asm volatile("st.shared::cluster.b64 [%0], %1;"
                         :: "r"(rbase + 0 * HP * 4), "l"(pk));
            *(float2*)(hl + 1 * HP) = make_float2(v0.y, v1.y);
            pk = pack2(v0.y, v1.y);
            asm volatile("st.shared::cluster.b64 [%0], %1;"
                         :: "r"(rbase + 1 * HP * 4), "l"(pk));
            *(float2*)(hl + 2 * HP) = make_float2(v0.z, v1.z);
            pk = pack2(v0.z, v1.z);
            asm volatile("st.shared::cluster.b64 [%0], %1;"
                         :: "r"(rbase + 2 * HP * 4), "l"(pk));
            *(float2*)(hl + 3 * HP) = make_float2(v0.w, v1.w);
            pk = pack2(v0.w, v1.w);
            asm volatile("st.shared::cluster.b64 [%0], %1;"
                         :: "r"(rbase + 3 * HP * 4), "l"(pk));
        }

        // 2-CTA cluster barrier: orders all shared::cluster stores, acts as
        // CTA barrier too (aligned, all threads).
        asm volatile("barrier.cluster.arrive.aligned;" ::: "memory");
        asm volatile("barrier.cluster.wait.aligned;"   ::: "memory");
    }
}

// ---------------------------------------------------------------------------
// Launch: 4 launches total (proj, rec) x 2 layers
// ---------------------------------------------------------------------------
extern "C" void kernel_launch(void* const* d_in, const int* in_sizes, int n_in,
                              void* d_out, int out_size)
{
    const float* x    = (const float*)d_in[0];
    const float* hx   = (const float*)d_in[1];
    const float* wih0 = (const float*)d_in[2];
    const float* whh0 = (const float*)d_in[3];
    const float* bih0 = (const float*)d_in[4];
    const float* bhh0 = (const float*)d_in[5];
    const float* wih1 = (const float*)d_in[6];
    const float* whh1 = (const float*)d_in[7];
    const float* bih1 = (const float*)d_in[8];
    const float* bhh1 = (const float*)d_in[9];

    float* out = (float*)d_out;                          // [B, T, N, H]
    float* hn  = out + (size_t)Bn * Tn * Nn * Hn;        // [B, L, N, H]

    // w_s[256][132] + hbuf[2][256][10] + red[128][4] ull
    const size_t rec_smem = (size_t)(256 * WP + 2 * 256 * HP) * sizeof(float)
                          + 128 * 4 * sizeof(ull);   // 159744 B
    cudaFuncSetAttribute(rec_kernel, cudaFuncAttributeMaxDynamicSharedMemorySize,
                         (int)rec_smem);

    dim3 pgrid(Tn * Nn / 64, Hn / 64, Bn);   // (512, 4, 8)
    dim3 rgrid(2, Bn * 8);                    // 128 CTAs = 64 clusters of 2

    // Layer 0
    proj_kernel<<<pgrid, 256>>>(x, wih0, bih0, bhh0);
    rec_kernel<<<rgrid, 256, rec_smem>>>(hx, whh0, nullptr, hn, 0);

    // Layer 1
    proj_kernel<<<pgrid, 256>>>(nullptr, wih1, bih1, bhh1);
    rec_kernel<<<rgrid, 256, rec_smem>>>(hx, whh1, out, hn, 1);
}

// round 14
// speedup vs baseline: 1.1156x; 1.1156x over previous
#include <cuda_runtime.h>
#include <cstddef>
#include <cstdint>

// Problem constants
#define Bn 8
#define Tn 512
#define Nn 64
#define Hn 256   // I == H == 256

typedef unsigned long long ull;

// ---------------------------------------------------------------------------
// Scratch (device globals: allocation-free rule)
// ---------------------------------------------------------------------------
__device__ float g_xin[(size_t)Bn * Tn * Nn * Hn];   // per-layer input projections
__device__ float g_y0 [(size_t)Bn * Tn * Nn * Hn];   // layer-0 outputs

// f32x2 packed helpers -------------------------------------------------------
__device__ __forceinline__ ull dup_f32(float x) {
    ull r;
    asm("mov.b64 %0, {%1, %1};" : "=l"(r) : "f"(x));
    return r;
}
__device__ __forceinline__ void fma2(ull& acc, ull a, ull b) {
    asm("fma.rn.f32x2 %0, %1, %2, %0;" : "+l"(acc) : "l"(a), "l"(b));
}
__device__ __forceinline__ void add2(ull& acc, ull v) {
    asm("add.rn.f32x2 %0, %0, %1;" : "+l"(acc) : "l"(v));
}
__device__ __forceinline__ void unpack2(ull v, float& lo, float& hi) {
    asm("mov.b64 {%0, %1}, %2;" : "=f"(lo), "=f"(hi) : "l"(v));
}
__device__ __forceinline__ ull pack2(float lo, float hi) {
    ull r;
    asm("mov.b64 %0, {%1, %2};" : "=l"(r) : "f"(lo), "f"(hi));
    return r;
}
__device__ __forceinline__ uint32_t smem_u32(const void* p) {
    uint32_t a;
    asm("{ .reg .u64 t; cvta.to.shared.u64 t, %1; cvt.u32.u64 %0, t; }"
        : "=r"(a) : "l"(p));
    return a;
}

// ---------------------------------------------------------------------------
// Projection (f32x2, v2): g_xin[b,m,j] = sum_i X[b,m,i]*W[b,j,i] + bih + bhh
//   64m x 64j tile, K=256. 256 threads, 2 CTAs/SM.
//   W tile loaded ONCE per block, k-major, stride 66 (LDS.64 conflict-free).
//   X staged m-major stride 36 per 32-k chunk (coalesced LDG, aligned LDS.128).
//   Per k-quad: 4 LDS.128 x + 8 LDS.64 w + 16 dup + 32 FFMA2 = 60 issues/64 FMA.
// ---------------------------------------------------------------------------
#define WSP 66   // Ws row stride (floats), k-major
#define XSP 36   // Xs row stride (floats), m-major

__global__ __launch_bounds__(256, 2) void proj_kernel(
    const float* __restrict__ Xext,
    const float* __restrict__ W,
    const float* __restrict__ bih,
    const float* __restrict__ bhh)
{
    extern __shared__ float psm[];
    float* Ws = psm;                 // [256][WSP]  Ws[k][j]
    float* Xs = psm + 256 * WSP;     // [64][XSP]   Xs[m][kc] per 32-k chunk

    const float* X = Xext ? Xext : g_y0;
    const int mt = blockIdx.x, jt = blockIdx.y, b = blockIdx.z;
    const int lin = threadIdx.x;
    const int tx = lin & 15, ty = lin >> 4;
    const int tx2 = tx * 2, ty4 = ty * 4;

    const float* Xb = X + ((size_t)b * (Tn * Nn) + mt * 64) * 256;
    const float* Wb = W + ((size_t)b * 256 + jt * 64) * 256;

    // One-time W tile load, transposed to k-major.
    // Mapping keeps LDG coalesced (8-lane 128B segments) and STS 2-way max:
    //   j = (lin>>3)&31 joined with iteration bit; kq = (lin&7) + 8*it_hi
#pragma unroll
    for (int it = 0; it < 16; ++it) {
        int j  = ((lin >> 3) & 31) | ((it & 1) << 5);
        int kq = (lin & 7) | ((it >> 1) << 3);
        int k  = kq * 4;
        float4 wv = *(const float4*)(Wb + (size_t)j * 256 + k);
        Ws[(k + 0) * WSP + j] = wv.x;
        Ws[(k + 1) * WSP + j] = wv.y;
        Ws[(k + 2) * WSP + j] = wv.z;
        Ws[(k + 3) * WSP + j] = wv.w;
    }

    ull a00 = 0, a01 = 0, a10 = 0, a11 = 0, a20 = 0, a21 = 0, a30 = 0, a31 = 0;

    for (int kk = 0; kk < 256; kk += 32) {
        __syncthreads();
        // Stage X chunk m-major: coalesced LDG, STS.128 (4-way worst case, x2)
#pragma unroll
        for (int r = 0; r < 2; ++r) {
            int f  = lin + r * 256;          // 512 float4 = 64m x 8 k-quads
            int m  = f >> 3;
            int kc = (f & 7) << 2;
            float4 xv = *(const float4*)(Xb + (size_t)m * 256 + kk + kc);
            *(float4*)(Xs + m * XSP + kc) = xv;
        }
        __syncthreads();

#pragma unroll
        for (int q = 0; q < 8; ++q) {
            float4 xv0 = *(const float4*)(Xs + (ty4 + 0) * XSP + 4 * q);
            float4 xv1 = *(const float4*)(Xs + (ty4 + 1) * XSP + 4 * q);
            float4 xv2 = *(const float4*)(Xs + (ty4 + 2) * XSP + 4 * q);
            float4 xv3 = *(const float4*)(Xs + (ty4 + 3) * XSP + 4 * q);
            const float* wrow = Ws + (size_t)(kk + 4 * q) * WSP;
#pragma unroll
            for (int dk = 0; dk < 4; ++dk) {
                ull w0 = *(const ull*)(wrow + dk * WSP + tx2);
                ull w1 = *(const ull*)(wrow + dk * WSP + tx2 + 32);
                float c0 = dk == 0 ? xv0.x : dk == 1 ? xv0.y : dk == 2 ? xv0.z : xv0.w;
                float c1 = dk == 0 ? xv1.x : dk == 1 ? xv1.y : dk == 2 ? xv1.z : xv1.w;
                float c2 = dk == 0 ? xv2.x : dk == 1 ? xv2.y : dk == 2 ? xv2.z : xv2.w;
                float c3 = dk == 0 ? xv3.x : dk == 1 ? xv3.y : dk == 2 ? xv3.z : xv3.w;
                ull d0 = dup_f32(c0), d1 = dup_f32(c1);
                ull d2 = dup_f32(c2), d3 = dup_f32(c3);
                fma2(a00, d0, w0); fma2(a01, d0, w1);
                fma2(a10, d1, w0); fma2(a11, d1, w1);
                fma2(a20, d2, w0); fma2(a21, d2, w1);
                fma2(a30, d3, w0); fma2(a31, d3, w1);
            }
        }
    }

    // Epilogue: add bias, store float2 pairs (coalesced per warp)
    const int j0 = jt * 64 + tx2, j1 = j0 + 32;
    float2 bi0 = *(const float2*)(bih + b * 256 + j0);
    float2 bh0 = *(const float2*)(bhh + b * 256 + j0);
    float2 bi1 = *(const float2*)(bih + b * 256 + j1);
    float2 bh1 = *(const float2*)(bhh + b * 256 + j1);
    const float b00 = bi0.x + bh0.x, b01 = bi0.y + bh0.y;
    const float b10 = bi1.x + bh1.x, b11 = bi1.y + bh1.y;

    const size_t mbase = (size_t)b * (Tn * Nn) + mt * 64 + ty4;
    ull accs[4][2] = {{a00, a01}, {a10, a11}, {a20, a21}, {a30, a31}};
#pragma unroll
    for (int i = 0; i < 4; ++i) {
        float lo, hi;
        unpack2(accs[i][0], lo, hi);
        *(float2*)(g_xin + (mbase + i) * 256 + j0) = make_float2(lo + b00, hi + b01);
        unpack2(accs[i][1], lo, hi);
        *(float2*)(g_xin + (mbase + i) * 256 + j1) = make_float2(lo + b10, hi + b11);
    }
}

// ---------------------------------------------------------------------------
// Recurrence: 512 sequential steps. (UNCHANGED — best known, R10)
//   64 clusters of 2 CTAs. Cluster = (instance b, n-octet). CTA = j-half (128 j).
//   Per-CTA: 8n x 128j x 256k per step; W half (128x256 f32) resident in SMEM.
//   h in SMEM (double-buffered); peer half written via DSMEM st.shared::cluster.
// ---------------------------------------------------------------------------
#define WP 132   // w_s row stride (floats)
#define HP 10    // h_buf row stride (floats)

__global__ __launch_bounds__(256) __cluster_dims__(2, 1, 1)
void rec_kernel(
    const float* __restrict__ hx,     // [B, L, N, H]
    const float* __restrict__ whh,    // [B, H, H]
    float* __restrict__ yext,         // layer outputs (nullptr -> g_y0)
    float* __restrict__ hn,           // [B, L, N, H] final hidden
    int layer)
{
    extern __shared__ float sm[];
    float* w_s  = sm;                       // [256][WP]  k-major, j-half fast
    float* hbuf = sm + 256 * WP;            // [2][256][HP] k = GLOBAL j index
    ull* red = (ull*)(sm + 256 * WP + 2 * 256 * HP);  // [128][4]

    const int jh  = blockIdx.x;             // j-half = cluster rank (0/1)
    const int bn  = blockIdx.y;             // b*8 + n-octet
    const int b   = bn >> 3, nch = bn & 7;
    const int lin = threadIdx.x;
    const int kh  = lin >> 7;               // k-half (warp-uniform)
    const int wl  = lin & 127;
    const int jc  = wl >> 5;                // j-chunk of 32 within half (0..3)
    const int lane = wl & 31;
    const int q   = lane & 7;               // j-quad (0..7)
    const int p   = lane >> 3;              // n-pair (0..3)
    const int jl  = jc * 32 + q * 4;        // j within half (0..124)
    const int p2  = p * 2;
    const int kbeg = kh << 7;

    float* y = yext ? yext : g_y0;

    // Resident W half, transposed k-major: w_s[k][j] = whh[b][jh*128+j][k]
    const float* wb = whh + ((size_t)b * 256 + jh * 128) * 256;
    for (int f = lin; f < 8192; f += 256) {       // 128 j x 64 float4
        int j = f >> 6, kc = (f & 63) << 2;
        float4 v = *(const float4*)(wb + (size_t)j * 256 + kc);
        w_s[(kc + 0) * WP + j] = v.x;
        w_s[(kc + 1) * WP + j] = v.y;
        w_s[(kc + 2) * WP + j] = v.z;
        w_s[(kc + 3) * WP + j] = v.w;
    }

    // t=0 h staging: full 256-k rows for our 8 n, transposed into hbuf[1]
    const float* h0 = hx + (size_t)(b * 2 + layer) * Nn * Hn + (size_t)nch * 8 * Hn;
    for (int f = lin; f < 2048; f += 256) {       // 8 n x 256 k scalars
        int n = f >> 8, k = f & 255;
        hbuf[(size_t)(256 + k) * HP + n] = h0[n * 256 + k];   // buffer 1
    }
    __syncthreads();

    // Peer DSMEM base for hbuf
    const uint32_t hbuf_local = smem_u32(hbuf);
    uint32_t hbuf_peer;
    asm("mapa.shared::cluster.u32 %0, %1, %2;"
        : "=r"(hbuf_peer) : "r"(hbuf_local), "r"(jh ^ 1));

    const int jrow0 = jh * 128 + jl;        // global j row base for our outputs
    const size_t xybase0 = (size_t)nch * 8 * Hn + jh * 128 + jl;

    for (int t = 0; t < Tn; ++t) {
        const float* hcur = hbuf + (size_t)(((t + 1) & 1) * 256) * HP;

        // Prefetch xin[t] fragment (lower half owns the epilogue)
        const size_t tb = ((size_t)b * Tn + t) * (Nn * Hn) + xybase0;
        float4 x0, x1;
        if (!kh) {
            x0 = __ldg((const float4*)(g_xin + tb + (size_t)(p2 + 0) * Hn));
            x1 = __ldg((const float4*)(g_xin + tb + (size_t)(p2 + 1) * Hn));
        }

        // Packed-f32x2 mainloop over this thread's k-half
        ull a00 = 0ull, a01 = 0ull, a10 = 0ull, a11 = 0ull;
#pragma unroll 8
        for (int k = kbeg; k < kbeg + 128; ++k) {
            float2 hv = *(const float2*)(hcur + (size_t)k * HP + p2);
            ulonglong2 wv = *(const ulonglong2*)(w_s + (size_t)k * WP + jl);
            ull h0d = dup_f32(hv.x);
            ull h1d = dup_f32(hv.y);
            fma2(a00, h0d, wv.x);
            fma2(a01, h0d, wv.y);
            fma2(a10, h1d, wv.x);
            fma2(a11, h1d, wv.y);
        }

        // Cross-half reduction through SMEM scratch
        if (kh) {
            ulonglong2* r = (ulonglong2*)(red + (size_t)wl * 4);
            r[0] = make_ulonglong2(a00, a01);
            r[1] = make_ulonglong2(a10, a11);
        }
        __syncthreads();

        if (!kh) {
            const ulonglong2* r = (const ulonglong2*)(red + (size_t)wl * 4);
            ulonglong2 q0 = r[0], q1 = r[1];
            add2(a00, q0.x); add2(a01, q0.y);
            add2(a10, q1.x); add2(a11, q1.y);

            float f00, f01, f02, f03, f10, f11, f12, f13;
            unpack2(a00, f00, f01); unpack2(a01, f02, f03);
            unpack2(a10, f10, f11); unpack2(a11, f12, f13);

            float4 v0, v1;
            v0.x = tanhf(f00 + x0.x); v0.y = tanhf(f01 + x0.y);
            v0.z = tanhf(f02 + x0.z); v0.w = tanhf(f03 + x0.w);
            v1.x = tanhf(f10 + x1.x); v1.y = tanhf(f11 + x1.y);
            v1.z = tanhf(f12 + x1.z); v1.w = tanhf(f13 + x1.w);

            // y (and hn) global stores
            float* yt = y + ((size_t)b * Tn + t) * (Nn * Hn) + xybase0;
            *(float4*)(yt + (size_t)(p2 + 0) * Hn) = v0;
            *(float4*)(yt + (size_t)(p2 + 1) * Hn) = v1;
            if (t == Tn - 1) {
                float* hnp = hn + (size_t)(b * 2 + layer) * Nn * Hn + xybase0;
                *(float4*)(hnp + (size_t)(p2 + 0) * Hn) = v0;
                *(float4*)(hnp + (size_t)(p2 + 1) * Hn) = v1;
            }

            // h stores: local + peer DSMEM, rows = global j, cols = local n-pair
            const int boff = (t & 1) * 256;
            float* hl = hbuf + (size_t)(boff + jrow0) * HP + p2;
            const uint32_t rbase = hbuf_peer
                + (uint32_t)(((boff + jrow0) * HP + p2) * sizeof(float));
            ull pk;

            *(float2*)(hl + 0 * HP) = make_float2(v0.x, v1.x);
            pk = pack2(v0.x, v1.x);
            asm volatile("st.shared::cluster.b64 [%0], %1;"
                         :: "r"(rbase + 0 * HP * 4), "l"(pk));
            *(float2*)(hl + 1 * HP) = make_float2(v0.y, v1.y);
            pk = pack2(v0.y, v1.y);
            asm volatile("st.shared::cluster.b64 [%0], %1;"
                         :: "r"(rbase + 1 * HP * 4), "l"(pk));
            *(float2*)(hl + 2 * HP) = make_float2(v0.z, v1.z);
            pk = pack2(v0.z, v1.z);
            asm volatile("st.shared::cluster.b64 [%0], %1;"
                         :: "r"(rbase + 2 * HP * 4), "l"(pk));
            *(float2*)(hl + 3 * HP) = make_float2(v0.w, v1.w);
            pk = pack2(v0.w, v1.w);
            asm volatile("st.shared::cluster.b64 [%0], %1;"
                         :: "r"(rbase + 3 * HP * 4), "l"(pk));
        }

        // 2-CTA cluster barrier: orders all shared::cluster stores, acts as
        // CTA barrier too (aligned, all threads).
        asm volatile("barrier.cluster.arrive.aligned;" ::: "memory");
        asm volatile("barrier.cluster.wait.aligned;"   ::: "memory");
    }
}

// ---------------------------------------------------------------------------
// Launch: 4 launches total (proj, rec) x 2 layers
// ---------------------------------------------------------------------------
extern "C" void kernel_launch(void* const* d_in, const int* in_sizes, int n_in,
                              void* d_out, int out_size)
{
    const float* x    = (const float*)d_in[0];
    const float* hx   = (const float*)d_in[1];
    const float* wih0 = (const float*)d_in[2];
    const float* whh0 = (const float*)d_in[3];
    const float* bih0 = (const float*)d_in[4];
    const float* bhh0 = (const float*)d_in[5];
    const float* wih1 = (const float*)d_in[6];
    const float* whh1 = (const float*)d_in[7];
    const float* bih1 = (const float*)d_in[8];
    const float* bhh1 = (const float*)d_in[9];

    float* out = (float*)d_out;                          // [B, T, N, H]
    float* hn  = out + (size_t)Bn * Tn * Nn * Hn;        // [B, L, N, H]

    // proj: Ws[256][66] + Xs[64][36]
    const size_t proj_smem = (size_t)(256 * WSP + 64 * XSP) * sizeof(float); // 76800
    cudaFuncSetAttribute(proj_kernel, cudaFuncAttributeMaxDynamicSharedMemorySize,
                         (int)proj_smem);

    // rec: w_s[256][132] + hbuf[2][256][10] + red[128][4] ull
    const size_t rec_smem = (size_t)(256 * WP + 2 * 256 * HP) * sizeof(float)
                          + 128 * 4 * sizeof(ull);   // 159744 B
    cudaFuncSetAttribute(rec_kernel, cudaFuncAttributeMaxDynamicSharedMemorySize,
                         (int)rec_smem);

    dim3 pgrid(Tn * Nn / 64, Hn / 64, Bn);   // (512, 4, 8)
    dim3 rgrid(2, Bn * 8);                    // 128 CTAs = 64 clusters of 2

    // Layer 0
    proj_kernel<<<pgrid, 256, proj_smem>>>(x, wih0, bih0, bhh0);
    rec_kernel<<<rgrid, 256, rec_smem>>>(hx, whh0, nullptr, hn, 0);

    // Layer 1
    proj_kernel<<<pgrid, 256, proj_smem>>>(nullptr, wih1, bih1, bhh1);
    rec_kernel<<<rgrid, 256, rec_smem>>>(hx, whh1, out, hn, 1);
}